// round 3
// baseline (speedup 1.0000x reference)
#include <cuda_runtime.h>
#include <stdint.h>

#define BATCH 16384
#define HID   512
#define KC    2048
#define LQ    4

#define BM 128
#define BN 128
#define BK 16

// ---------------- scratch (device globals: allocation-free) ----------------
__device__ float g_R[(size_t)BATCH * HID];            // residual / projected x (32 MB)
__device__ float g_rnorm[BATCH];                      // ||residual_row||^2
__device__ float g_cnorm[LQ * KC];                    // ||codeword||^2
__device__ unsigned long long g_part[(size_t)BATCH * 16];  // per-row partial argmins

// ---------------- helpers ----------------
__device__ __forceinline__ float blk_sum128(float v) {
    #pragma unroll
    for (int o = 16; o; o >>= 1) v += __shfl_xor_sync(0xffffffffu, v, o);
    __shared__ float sm[4];
    if ((threadIdx.x & 31) == 0) sm[threadIdx.x >> 5] = v;
    __syncthreads();
    return sm[0] + sm[1] + sm[2] + sm[3];
}

// ||codeword||^2 for all L*K codewords. 1 block per codeword, 128 threads.
__global__ void cnorm_kernel(const float* __restrict__ cb) {
    const float4* p = reinterpret_cast<const float4*>(cb) + (size_t)blockIdx.x * (HID / 4);
    float4 v = p[threadIdx.x];
    float s = blk_sum128(v.x * v.x + v.y * v.y + v.z * v.z + v.w * v.w);
    if (threadIdx.x == 0) g_cnorm[blockIdx.x] = s;
}

// ||R_row||^2 (only needed once, before level 0)
__global__ void rnorm_kernel() {
    const float4* p = reinterpret_cast<const float4*>(g_R) + (size_t)blockIdx.x * (HID / 4);
    float4 v = p[threadIdx.x];
    float s = blk_sum128(v.x * v.x + v.y * v.y + v.z * v.z + v.w * v.w);
    if (threadIdx.x == 0) g_rnorm[blockIdx.x] = s;
}

// ---------------- fused NT GEMM ----------------
// C[m][n] = sum_k A[m][k] * B[n][k]   (both row-major, k contiguous)
// MODE 0: projection -> writes g_R (+bias), zeroes qsum region of d_out
// MODE 1: distance   -> writes -dist into logits, per-row partial argmin into g_part
#define STORE_TILE(b)                                                     \
    As[b][lko + 0][lrow] = ra0.x; As[b][lko + 1][lrow] = ra0.y;           \
    As[b][lko + 2][lrow] = ra0.z; As[b][lko + 3][lrow] = ra0.w;           \
    As[b][lko + 4][lrow] = ra1.x; As[b][lko + 5][lrow] = ra1.y;           \
    As[b][lko + 6][lrow] = ra1.z; As[b][lko + 7][lrow] = ra1.w;           \
    Bs[b][lko + 0][lrow] = rb0.x; Bs[b][lko + 1][lrow] = rb0.y;           \
    Bs[b][lko + 2][lrow] = rb0.z; Bs[b][lko + 3][lrow] = rb0.w;           \
    Bs[b][lko + 4][lrow] = rb1.x; Bs[b][lko + 5][lrow] = rb1.y;           \
    Bs[b][lko + 6][lrow] = rb1.z; Bs[b][lko + 7][lrow] = rb1.w;

#define COMPUTE(b)                                                        \
    _Pragma("unroll")                                                     \
    for (int kk = 0; kk < BK; kk++) {                                     \
        float4 a0 = *(const float4*)&As[b][kk][ty * 4];                   \
        float4 a1 = *(const float4*)&As[b][kk][ty * 4 + 64];              \
        float4 b0 = *(const float4*)&Bs[b][kk][tx * 4];                   \
        float4 b1 = *(const float4*)&Bs[b][kk][tx * 4 + 64];              \
        float av[8] = {a0.x, a0.y, a0.z, a0.w, a1.x, a1.y, a1.z, a1.w};   \
        float bv[8] = {b0.x, b0.y, b0.z, b0.w, b1.x, b1.y, b1.z, b1.w};   \
        _Pragma("unroll")                                                 \
        for (int i = 0; i < 8; i++)                                       \
            _Pragma("unroll")                                             \
            for (int j = 0; j < 8; j++)                                   \
                acc[i][j] = fmaf(av[i], bv[j], acc[i][j]);                \
    }

template <int MODE>
__global__ __launch_bounds__(256, 2) void gemm_nt(
    const float* __restrict__ A,     // MODE0: features
    const float* __restrict__ Bm,    // MODE0: W_proj ; MODE1: codebooks base
    const float* __restrict__ bias,  // MODE0: b_proj
    float* __restrict__ out,         // MODE1: logits base
    float* __restrict__ qsum,        // MODE0: qsum region (zeroed here)
    int l)
{
    __shared__ __align__(16) float As[2][BK][BM];
    __shared__ __align__(16) float Bs[2][BK][BN];

    const int tid = threadIdx.x;
    const int ty  = tid >> 4;
    const int tx  = tid & 15;
    const int bn  = blockIdx.x;
    const int bm  = blockIdx.y;

    const float* Abase = (MODE == 0) ? A : g_R;
    const float* Bbase = (MODE == 0) ? Bm : (Bm + (size_t)l * KC * HID);

    const int lrow = tid >> 1;
    const int lko  = (tid & 1) * 8;
    const float* Arow = Abase + (size_t)(bm * BM + lrow) * HID + lko;
    const float* Brow = Bbase + (size_t)(bn * BN + lrow) * HID + lko;

    float acc[8][8];
    #pragma unroll
    for (int i = 0; i < 8; i++)
        #pragma unroll
        for (int j = 0; j < 8; j++) acc[i][j] = 0.0f;

    // prologue: tile 0
    float4 ra0 = *(const float4*)(Arow);
    float4 ra1 = *(const float4*)(Arow + 4);
    float4 rb0 = *(const float4*)(Brow);
    float4 rb1 = *(const float4*)(Brow + 4);
    STORE_TILE(0)
    __syncthreads();

    int buf = 0;
    #pragma unroll 1
    for (int kt = 1; kt < HID / BK; kt++) {
        ra0 = *(const float4*)(Arow + kt * BK);
        ra1 = *(const float4*)(Arow + kt * BK + 4);
        rb0 = *(const float4*)(Brow + kt * BK);
        rb1 = *(const float4*)(Brow + kt * BK + 4);
        COMPUTE(buf)
        const int nb = buf ^ 1;
        STORE_TILE(nb)
        __syncthreads();
        buf = nb;
    }
    COMPUTE(buf)

    // thread's 8 rows / 8 cols (two groups of 4, 64 apart)
    int rows[8], cols[8];
    #pragma unroll
    for (int i = 0; i < 4; i++) {
        rows[i] = ty * 4 + i;  rows[i + 4] = 64 + ty * 4 + i;
        cols[i] = tx * 4 + i;  cols[i + 4] = 64 + tx * 4 + i;
    }

    if (MODE == 0) {
        const int gc0 = bn * BN + tx * 4;
        const int gc1 = gc0 + 64;
        float4 bz0 = *(const float4*)(bias + gc0);
        float4 bz1 = *(const float4*)(bias + gc1);
        float4 z = make_float4(0.f, 0.f, 0.f, 0.f);
        #pragma unroll
        for (int i = 0; i < 8; i++) {
            const int gr = bm * BM + rows[i];
            float4 v0 = make_float4(acc[i][0] + bz0.x, acc[i][1] + bz0.y,
                                    acc[i][2] + bz0.z, acc[i][3] + bz0.w);
            float4 v1 = make_float4(acc[i][4] + bz1.x, acc[i][5] + bz1.y,
                                    acc[i][6] + bz1.z, acc[i][7] + bz1.w);
            *(float4*)(g_R + (size_t)gr * HID + gc0) = v0;
            *(float4*)(g_R + (size_t)gr * HID + gc1) = v1;
            *(float4*)(qsum + (size_t)gr * HID + gc0) = z;
            *(float4*)(qsum + (size_t)gr * HID + gc1) = z;
        }
    } else {
        __shared__ unsigned long long red[BM];
        if (tid < BM) red[tid] = ~0ull;
        __syncthreads();

        float cn[8];
        #pragma unroll
        for (int j = 0; j < 8; j++) cn[j] = g_cnorm[l * KC + bn * BN + cols[j]];

        #pragma unroll
        for (int i = 0; i < 8; i++) {
            const int lr = rows[i];
            const int gr = bm * BM + lr;
            const float rn = g_rnorm[gr];
            float o[8];
            unsigned long long best = ~0ull;
            #pragma unroll
            for (int j = 0; j < 8; j++) {
                float d2   = rn + cn[j] - 2.0f * acc[i][j];
                float dist = sqrtf(fmaxf(d2, 0.0f));
                o[j] = -dist;
                unsigned long long cand =
                    ((unsigned long long)__float_as_uint(dist) << 32) |
                    (unsigned)(bn * BN + cols[j]);
                if (cand < best) best = cand;
            }
            float* obase = out + (size_t)gr * (LQ * KC) + (size_t)l * KC + bn * BN;
            *(float4*)(obase + tx * 4)      = make_float4(o[0], o[1], o[2], o[3]);
            *(float4*)(obase + 64 + tx * 4) = make_float4(o[4], o[5], o[6], o[7]);
            atomicMin(&red[lr], best);
        }
        __syncthreads();
        if (tid < BM) g_part[(size_t)(bm * BM + tid) * 16 + bn] = red[tid];
    }
}

// reduce 16 partial argmins -> id; residual -= cb[id]; qsum += cb[id]; next rnorm.
__global__ void update_kernel(const float* __restrict__ cb, float* __restrict__ qsum, int l) {
    const int row = blockIdx.x;
    const int tid = threadIdx.x;
    __shared__ int s_id;
    if (tid < 32) {
        unsigned long long v = (tid < 16) ? g_part[(size_t)row * 16 + tid] : ~0ull;
        #pragma unroll
        for (int o = 16; o; o >>= 1) {
            unsigned long long w = __shfl_xor_sync(0xffffffffu, v, o);
            if (w < v) v = w;
        }
        if (tid == 0) s_id = (int)(unsigned)(v & 0xffffffffull);
    }
    __syncthreads();
    const int id = s_id;

    const float4* c4 = (const float4*)(cb + ((size_t)l * KC + id) * HID);
    float4* r4 = (float4*)(g_R + (size_t)row * HID);
    float4* q4 = (float4*)(qsum + (size_t)row * HID);

    float4 c = c4[tid];
    float4 r = r4[tid];
    r.x -= c.x; r.y -= c.y; r.z -= c.z; r.w -= c.w;
    r4[tid] = r;
    float4 q = q4[tid];
    q.x += c.x; q.y += c.y; q.z += c.z; q.w += c.w;
    q4[tid] = q;

    float s = blk_sum128(r.x * r.x + r.y * r.y + r.z * r.z + r.w * r.w);
    if (tid == 0) g_rnorm[row] = s;
}

// ---------------- launch ----------------
extern "C" void kernel_launch(void* const* d_in, const int* in_sizes, int n_in,
                              void* d_out, int out_size) {
    (void)in_sizes; (void)n_in; (void)out_size;
    const float* features = (const float*)d_in[0];   // [16384, 512]
    const float* W        = (const float*)d_in[1];   // [512, 512]
    const float* bvec     = (const float*)d_in[2];   // [512]
    const float* cb       = (const float*)d_in[3];   // [4, 2048, 512]

    float* logits = (float*)d_out;                              // [B, L, K]
    float* qsum   = logits + (size_t)BATCH * LQ * KC;           // [B, D]

    cnorm_kernel<<<LQ * KC, 128>>>(cb);
    gemm_nt<0><<<dim3(HID / BN, BATCH / BM), 256>>>(features, W, bvec, nullptr, qsum, 0);
    rnorm_kernel<<<BATCH, 128>>>();
    for (int l = 0; l < LQ; l++) {
        gemm_nt<1><<<dim3(KC / BN, BATCH / BM), 256>>>(nullptr, cb, nullptr, logits, nullptr, l);
        update_kernel<<<BATCH, 128>>>(cb, qsum, l);
    }
}